// round 10
// baseline (speedup 1.0000x reference)
#include <cuda_runtime.h>
#include <cuda_fp16.h>
#include <stdint.h>
#include <string.h>

#define T_TOK 2048
#define H_DIM 2048
#define I_DIM 1408
#define NE    8
#define GS    128
#define BM    128
#define BK    64
#define LDSW  72          // padded A/Bf16 row stride in halves (144 B)

// smem layout (bytes, per block)
#define A_ST     18432            // one A stage: 128 rows x 144 B
#define BI_BASE  36864            // after 2 A stages
#define BI_ST    16384            // one Bint stage: 64 rows x 256 B
#define BF_BASE  69632            // after 2 Bint stages
#define BF_ST    9216             // one Bf16 stage: 64 rows x 144 B
#define SC_BASE  88064            // scales: 64 x 16 floats
#define GSMEM    92160

// ---- persistent device scratch ----
__device__ int    g_cnt[NE];
__device__ int    g_tok[NE * T_TOK];
__device__ float  g_rw [NE * T_TOK];
__device__ __half g_x  [(size_t)T_TOK * H_DIM];
__device__ __half g_act[(size_t)NE * T_TOK * I_DIM];

// ---------------- helpers ----------------
__device__ __forceinline__ uint32_t h2u(__half2 h) { uint32_t u; memcpy(&u, &h, 4); return u; }
__device__ __forceinline__ uint32_t smem_u32(const void* p) {
    uint32_t a;
    asm("{ .reg .u64 t; cvta.to.shared.u64 t, %1; cvt.u32.u64 %0, t; }" : "=r"(a) : "l"(p));
    return a;
}
__device__ __forceinline__ void ldm_x4(uint32_t* r, uint32_t addr) {
    asm volatile("ldmatrix.sync.aligned.m8n8.x4.shared.b16 {%0,%1,%2,%3}, [%4];"
        : "=r"(r[0]), "=r"(r[1]), "=r"(r[2]), "=r"(r[3]) : "r"(addr));
}
__device__ __forceinline__ void mma16816(float* d, const uint32_t* a, const uint32_t* b) {
    asm volatile("mma.sync.aligned.m16n8k16.row.col.f32.f16.f16.f32 "
        "{%0,%1,%2,%3}, {%4,%5,%6,%7}, {%8,%9}, {%0,%1,%2,%3};"
        : "+f"(d[0]), "+f"(d[1]), "+f"(d[2]), "+f"(d[3])
        : "r"(a[0]), "r"(a[1]), "r"(a[2]), "r"(a[3]), "r"(b[0]), "r"(b[1]));
}
__device__ __forceinline__ void cp16(uint32_t dst, const void* src) {
    asm volatile("cp.async.cg.shared.global [%0], [%1], 16;" :: "r"(dst), "l"(src));
}
#define CP_COMMIT()  asm volatile("cp.async.commit_group;")
#define CP_WAIT(n)   asm volatile("cp.async.wait_group %0;" :: "n"(n))

// ---------------- L0: zero output + counters ----------------
__global__ void zero_kernel(float* __restrict__ out, int n) {
    int i = blockIdx.x * blockDim.x + threadIdx.x;
    if (i < n) out[i] = 0.0f;
    if (i < NE) g_cnt[i] = 0;
}

// ---------------- L1: routing ----------------
__global__ void route_kernel(const float* __restrict__ logits) {
    int t = blockIdx.x * blockDim.x + threadIdx.x;
    if (t >= T_TOK) return;
    float v[NE];
#pragma unroll
    for (int e = 0; e < NE; ++e) v[e] = logits[t * NE + e];
    int i0 = 0;
#pragma unroll
    for (int e = 1; e < NE; ++e) if (v[e] > v[i0]) i0 = e;
    int i1 = (i0 == 0) ? 1 : 0;
#pragma unroll
    for (int e = 0; e < NE; ++e) if (e != i0 && v[e] > v[i1]) i1 = e;
    float ex = __expf(v[i1] - v[i0]);
    float w0 = 1.0f / (1.0f + ex);
    float w1 = ex * w0;
    int p0 = atomicAdd(&g_cnt[i0], 1);
    g_tok[i0 * T_TOK + p0] = t;  g_rw[i0 * T_TOK + p0] = w0;
    int p1 = atomicAdd(&g_cnt[i1], 1);
    g_tok[i1 * T_TOK + p1] = t;  g_rw[i1 * T_TOK + p1] = w1;
}

// ---------------- L2: x fp32 -> fp16 ----------------
__global__ void convert_x_kernel(const float* __restrict__ x) {
    size_t i = ((size_t)blockIdx.x * 256 + threadIdx.x) * 8;
    float4 a = *(const float4*)(x + i);
    float4 b = *(const float4*)(x + i + 4);
    uint4 o;
    o.x = h2u(__floats2half2_rn(a.x, a.y));
    o.y = h2u(__floats2half2_rn(a.z, a.w));
    o.z = h2u(__floats2half2_rn(b.x, b.y));
    o.w = h2u(__floats2half2_rn(b.z, b.w));
    *(uint4*)(g_x + i) = o;
}

// =================================================================
// GEMM1: g_x @ Wgate/Wup (int4 inline-dequant), fused SwiGLU -> g_act.
// BM=128, 32 gate + 32 up outputs, BK=64. 2-stage A/Bint/Bf16.
// Per slab: cp.wait -> sync -> convert(s)+prefetch(s+1) -> sync -> mma(s).
// =================================================================
__global__ __launch_bounds__(256, 2) void gemm1_kernel(
    const int* __restrict__ qw, const float* __restrict__ sc)
{
    const int e   = blockIdx.z;
    const int cnt = g_cnt[e];
    const int m0  = blockIdx.x * BM;
    if (m0 >= cnt) return;
    const int n0  = blockIdx.y * 32;

    extern __shared__ char smem[];
    const uint32_t sb = smem_u32(smem);
    float* ssc = (float*)(smem + SC_BASE);

    const int tid = threadIdx.x, lane = tid & 31, wid = tid >> 5;
    const int warp_m = wid & 3, warp_n = wid >> 2;

    // scales: 64 rows x 16 groups
#pragma unroll
    for (int i = tid; i < 64 * 16; i += 256) {
        int r = i >> 4, g = i & 15;
        int grow = (r < 32) ? (n0 + r) : (I_DIM + n0 + r - 32);
        ssc[i] = sc[((size_t)e * 2 * I_DIM + grow) * (H_DIM / GS) + g];
    }

    // A loader: 128 rows x 128 B per slab, 2 threads/row, 4 cp16 each
    const int arow = tid >> 1, aseg = tid & 1;
    int am = m0 + arow; if (am >= cnt) am = cnt - 1;
    const __half* asrc = g_x + (size_t)g_tok[e * T_TOK + am] * H_DIM + aseg * 32;
    const uint32_t adst = sb + (uint32_t)(arow * 144 + aseg * 64);

    // Bint loader: 64 rows x 256 B per slab, 4 threads/row, 4 cp16 each
    const int brow = tid >> 2, bseg = tid & 3;
    const int grow = (brow < 32) ? (n0 + brow) : (I_DIM + n0 + brow - 32);
    const int* bsrc = qw + ((size_t)e * 2 * I_DIM + grow) * H_DIM + bseg * 16;
    const uint32_t bidst = sb + BI_BASE + (uint32_t)(brow * 256 + bseg * 64);

    float accg[2][2][4], accu[2][2][4];
#pragma unroll
    for (int a = 0; a < 2; ++a)
#pragma unroll
        for (int b = 0; b < 2; ++b)
#pragma unroll
            for (int c = 0; c < 4; ++c) { accg[a][b][c] = 0.f; accu[a][b][c] = 0.f; }

    // ldmatrix offsets
    const int arow0 = warp_m * 32 + (lane & 15);
    const int acol  = (lane >> 4) * 8;
    const int browl = (lane & 7) + ((lane >> 4) << 3);
    const int bcol  = ((lane >> 3) & 1) * 8;
    const uint32_t aoff0 = (uint32_t)((arow0 * LDSW + acol) * 2);
    const uint32_t aoff1 = (uint32_t)(((arow0 + 16) * LDSW + acol) * 2);
    const uint32_t bgoff = (uint32_t)(((warp_n * 16 + browl) * LDSW + bcol) * 2);
    const uint32_t buoff = bgoff + 32 * 144;

    // prologue: slab 0
#pragma unroll
    for (int c = 0; c < 4; ++c) cp16(adst + c * 16, asrc + c * 8);
#pragma unroll
    for (int c = 0; c < 4; ++c) cp16(bidst + c * 16, bsrc + c * 4);
    CP_COMMIT();

    const int S = H_DIM / BK;   // 32
    for (int s = 0; s < S; ++s) {
        CP_WAIT(0);
        __syncthreads();   // A(s), Bint(s) visible; mma(s-1) reads complete

        // convert Bint(s) -> Bf16(s&1)
        {
            const float sv = ssc[brow * 16 + (s >> 1)];
            const float ns = -8.0f * sv;
            const char* bi = smem + BI_BASE + (s & 1) * BI_ST + brow * 256 + bseg * 64;
            uint32_t o[8];
#pragma unroll
            for (int c = 0; c < 4; ++c) {
                const int4 v = *(const int4*)(bi + c * 16);
                float f0 = fmaf((float)v.x, sv, ns);
                float f1 = fmaf((float)v.y, sv, ns);
                float f2 = fmaf((float)v.z, sv, ns);
                float f3 = fmaf((float)v.w, sv, ns);
                o[c * 2 + 0] = h2u(__floats2half2_rn(f0, f1));
                o[c * 2 + 1] = h2u(__floats2half2_rn(f2, f3));
            }
            uint4* bf = (uint4*)(smem + BF_BASE + (s & 1) * BF_ST + brow * 144 + bseg * 32);
            bf[0] = make_uint4(o[0], o[1], o[2], o[3]);
            bf[1] = make_uint4(o[4], o[5], o[6], o[7]);
        }
        // prefetch slab s+1
        if (s + 1 < S) {
            const uint32_t ast = (uint32_t)(((s + 1) & 1) * A_ST);
            const uint32_t bst = (uint32_t)(((s + 1) & 1) * BI_ST);
            const int kb = (s + 1) * BK;
#pragma unroll
            for (int c = 0; c < 4; ++c) cp16(adst + ast + c * 16, asrc + kb + c * 8);
#pragma unroll
            for (int c = 0; c < 4; ++c) cp16(bidst + bst + c * 16, bsrc + kb + c * 4);
        }
        CP_COMMIT();
        __syncthreads();   // Bf16(s) visible

        const uint32_t sa  = sb + (uint32_t)((s & 1) * A_ST);
        const uint32_t sbf = sb + BF_BASE + (uint32_t)((s & 1) * BF_ST);
#pragma unroll
        for (int ks = 0; ks < 4; ++ks) {
            const uint32_t kb2 = (uint32_t)(ks * 32);
            uint32_t A[2][4], Bg[4], Bu[4];
            ldm_x4(A[0], sa + aoff0 + kb2);
            ldm_x4(A[1], sa + aoff1 + kb2);
            ldm_x4(Bg, sbf + bgoff + kb2);
            ldm_x4(Bu, sbf + buoff + kb2);
#pragma unroll
            for (int mf = 0; mf < 2; ++mf)
#pragma unroll
                for (int nf = 0; nf < 2; ++nf) {
                    mma16816(accg[mf][nf], A[mf], &Bg[nf * 2]);
                    mma16816(accu[mf][nf], A[mf], &Bu[nf * 2]);
                }
        }
    }

    // epilogue: SwiGLU -> g_act
#pragma unroll
    for (int mf = 0; mf < 2; ++mf) {
#pragma unroll
        for (int hr = 0; hr < 2; ++hr) {
            const int m = m0 + warp_m * 32 + mf * 16 + (lane >> 2) + hr * 8;
            if (m >= cnt) continue;
            __half* arow_p = g_act + ((size_t)e * T_TOK + m) * I_DIM;
#pragma unroll
            for (int nf = 0; nf < 2; ++nf) {
                const int c = n0 + warp_n * 16 + nf * 8 + (lane & 3) * 2;
                const float g0 = accg[mf][nf][hr * 2 + 0];
                const float g1 = accg[mf][nf][hr * 2 + 1];
                const float u0 = accu[mf][nf][hr * 2 + 0];
                const float u1 = accu[mf][nf][hr * 2 + 1];
                const float a0 = g0 / (1.0f + __expf(-g0)) * u0;
                const float a1 = g1 / (1.0f + __expf(-g1)) * u1;
                *(__half2*)&arow_p[c] = __floats2half2_rn(a0, a1);
            }
        }
    }
}

// =================================================================
// GEMM2: g_act @ Wdown (int4 inline-dequant), route-weighted atomicAdd.
// BM=128, BN=64, BK=64. Same pipeline structure.
// =================================================================
__global__ __launch_bounds__(256, 2) void gemm2_kernel(
    const int* __restrict__ qw, const float* __restrict__ sc, float* __restrict__ out)
{
    const int e   = blockIdx.z;
    const int cnt = g_cnt[e];
    const int m0  = blockIdx.x * BM;
    if (m0 >= cnt) return;
    const int n0  = blockIdx.y * 64;

    extern __shared__ char smem[];
    const uint32_t sb = smem_u32(smem);
    float* ssc = (float*)(smem + SC_BASE);

    const int tid = threadIdx.x, lane = tid & 31, wid = tid >> 5;
    const int warp_m = wid & 3, warp_n = wid >> 2;

#pragma unroll
    for (int i = tid; i < 64 * 16; i += 256) {
        int r = i >> 4, g = i & 15;
        ssc[i] = (g < I_DIM / GS)
            ? sc[((size_t)e * H_DIM + n0 + r) * (I_DIM / GS) + g] : 0.0f;
    }

    const int arow = tid >> 1, aseg = tid & 1;
    int am = m0 + arow; if (am >= cnt) am = cnt - 1;
    const __half* asrc = g_act + ((size_t)e * T_TOK + am) * I_DIM + aseg * 32;
    const uint32_t adst = sb + (uint32_t)(arow * 144 + aseg * 64);

    const int brow = tid >> 2, bseg = tid & 3;
    const int* bsrc = qw + ((size_t)e * H_DIM + n0 + brow) * I_DIM + bseg * 16;
    const uint32_t bidst = sb + BI_BASE + (uint32_t)(brow * 256 + bseg * 64);

    float acc[2][4][4];
#pragma unroll
    for (int a = 0; a < 2; ++a)
#pragma unroll
        for (int b = 0; b < 4; ++b)
#pragma unroll
            for (int c = 0; c < 4; ++c) acc[a][b][c] = 0.f;

    const int arow0 = warp_m * 32 + (lane & 15);
    const int acol  = (lane >> 4) * 8;
    const int browl = (lane & 7) + ((lane >> 4) << 3);
    const int bcol  = ((lane >> 3) & 1) * 8;
    const uint32_t aoff0 = (uint32_t)((arow0 * LDSW + acol) * 2);
    const uint32_t aoff1 = (uint32_t)(((arow0 + 16) * LDSW + acol) * 2);
    uint32_t boff[2];
#pragma unroll
    for (int bb = 0; bb < 2; ++bb)
        boff[bb] = (uint32_t)(((warp_n * 32 + bb * 16 + browl) * LDSW + bcol) * 2);

#pragma unroll
    for (int c = 0; c < 4; ++c) cp16(adst + c * 16, asrc + c * 8);
#pragma unroll
    for (int c = 0; c < 4; ++c) cp16(bidst + c * 16, bsrc + c * 4);
    CP_COMMIT();

    const int S = I_DIM / BK;   // 22
    for (int s = 0; s < S; ++s) {
        CP_WAIT(0);
        __syncthreads();

        {
            const float sv = ssc[brow * 16 + (s >> 1)];
            const float ns = -8.0f * sv;
            const char* bi = smem + BI_BASE + (s & 1) * BI_ST + brow * 256 + bseg * 64;
            uint32_t o[8];
#pragma unroll
            for (int c = 0; c < 4; ++c) {
                const int4 v = *(const int4*)(bi + c * 16);
                float f0 = fmaf((float)v.x, sv, ns);
                float f1 = fmaf((float)v.y, sv, ns);
                float f2 = fmaf((float)v.z, sv, ns);
                float f3 = fmaf((float)v.w, sv, ns);
                o[c * 2 + 0] = h2u(__floats2half2_rn(f0, f1));
                o[c * 2 + 1] = h2u(__floats2half2_rn(f2, f3));
            }
            uint4* bf = (uint4*)(smem + BF_BASE + (s & 1) * BF_ST + brow * 144 + bseg * 32);
            bf[0] = make_uint4(o[0], o[1], o[2], o[3]);
            bf[1] = make_uint4(o[4], o[5], o[6], o[7]);
        }
        if (s + 1 < S) {
            const uint32_t ast = (uint32_t)(((s + 1) & 1) * A_ST);
            const uint32_t bst = (uint32_t)(((s + 1) & 1) * BI_ST);
            const int kb = (s + 1) * BK;
#pragma unroll
            for (int c = 0; c < 4; ++c) cp16(adst + ast + c * 16, asrc + kb + c * 8);
#pragma unroll
            for (int c = 0; c < 4; ++c) cp16(bidst + bst + c * 16, bsrc + kb + c * 4);
        }
        CP_COMMIT();
        __syncthreads();

        const uint32_t sa  = sb + (uint32_t)((s & 1) * A_ST);
        const uint32_t sbf = sb + BF_BASE + (uint32_t)((s & 1) * BF_ST);
#pragma unroll
        for (int ks = 0; ks < 4; ++ks) {
            const uint32_t kb2 = (uint32_t)(ks * 32);
            uint32_t A[2][4], B[2][4];
            ldm_x4(A[0], sa + aoff0 + kb2);
            ldm_x4(A[1], sa + aoff1 + kb2);
            ldm_x4(B[0], sbf + boff[0] + kb2);
            ldm_x4(B[1], sbf + boff[1] + kb2);
#pragma unroll
            for (int mf = 0; mf < 2; ++mf)
#pragma unroll
                for (int nf = 0; nf < 4; ++nf)
                    mma16816(acc[mf][nf], A[mf], &B[nf >> 1][(nf & 1) * 2]);
        }
    }

    // epilogue: route-weighted scatter-add
#pragma unroll
    for (int mf = 0; mf < 2; ++mf) {
#pragma unroll
        for (int hr = 0; hr < 2; ++hr) {
            const int m = m0 + warp_m * 32 + mf * 16 + (lane >> 2) + hr * 8;
            if (m >= cnt) continue;
            const int   tok = g_tok[e * T_TOK + m];
            const float rw  = g_rw [e * T_TOK + m];
            float* orow = out + (size_t)tok * H_DIM;
#pragma unroll
            for (int nf = 0; nf < 4; ++nf) {
                const int c = n0 + warp_n * 32 + nf * 8 + (lane & 3) * 2;
                atomicAdd(&orow[c],     rw * acc[mf][nf][hr * 2 + 0]);
                atomicAdd(&orow[c + 1], rw * acc[mf][nf][hr * 2 + 1]);
            }
        }
    }
}

// ---------------------------------------------------------------
extern "C" void kernel_launch(void* const* d_in, const int* in_sizes, int n_in,
                              void* d_out, int out_size) {
    const float* logits = (const float*)d_in[0];
    const float* x      = (const float*)d_in[1];
    const int*   qgu    = (const int*)  d_in[2];
    const float* sgu    = (const float*)d_in[3];
    const int*   qd     = (const int*)  d_in[4];
    const float* sd     = (const float*)d_in[5];
    float* out = (float*)d_out;

    cudaFuncSetAttribute(gemm1_kernel, cudaFuncAttributeMaxDynamicSharedMemorySize, GSMEM);
    cudaFuncSetAttribute(gemm2_kernel, cudaFuncAttributeMaxDynamicSharedMemorySize, GSMEM);

    const int n_out = T_TOK * H_DIM;
    zero_kernel<<<(n_out + 255) / 256, 256>>>(out, n_out);
    route_kernel<<<(T_TOK + 127) / 128, 128>>>(logits);
    convert_x_kernel<<<2048, 256>>>(x);

    dim3 g1(T_TOK / BM, I_DIM / 32, NE);   // (16, 44, 8), m fastest
    gemm1_kernel<<<g1, 256, GSMEM>>>(qgu, sgu);

    dim3 g2(T_TOK / BM, H_DIM / 64, NE);   // (16, 32, 8)
    gemm2_kernel<<<g2, 256, GSMEM>>>(qd, sd, out);
}

// round 11
// speedup vs baseline: 1.6751x; 1.6751x over previous
#include <cuda_runtime.h>
#include <cuda_fp16.h>
#include <stdint.h>
#include <string.h>

#define T_TOK 2048
#define H_DIM 2048
#define I_DIM 1408
#define NE    8
#define GS    128
#define BM    128
#define BK    64
#define LDSW  72                        // smem row stride in halves (144B)
#define A_OFF_B   (128 * LDSW * 2)      // B tile byte offset within a stage (gemm1)
#define STAGE_B   (2 * 128 * LDSW * 2)  // gemm1 stage bytes (A + B tiles)
#define NSTAGE    3
#define SMEM_BYTES (NSTAGE * STAGE_B)   // gemm1: 110592 B

// gemm2 (BN=64, 2-stage) smem layout
#define G2_A_ST   (128 * LDSW * 2)      // 18432 B A tile
#define G2_B_ST   (64 * LDSW * 2)       // 9216 B B tile
#define G2_STAGE  (G2_A_ST + G2_B_ST)   // 27648 B
#define G2_SMEM   (2 * G2_STAGE)        // 55296 B -> 3 CTAs/SM (reg-capped)

// ---- persistent device scratch (no runtime allocation) ----
__device__ int    g_cnt[NE];
__device__ int    g_tok[NE * T_TOK];
__device__ float  g_rw [NE * T_TOK];
__device__ __half g_x  [(size_t)T_TOK * H_DIM];
__device__ __half g_act[(size_t)NE * T_TOK * I_DIM];
__device__ __half g_wgu[(size_t)NE * 2 * I_DIM * H_DIM];  // 92 MB fp16 dequant
__device__ __half g_wd [(size_t)NE * H_DIM * I_DIM];      // 46 MB fp16 dequant

// ---------------- helpers ----------------
__device__ __forceinline__ uint32_t h2u(__half2 h) { uint32_t u; memcpy(&u, &h, 4); return u; }
__device__ __forceinline__ uint32_t smem_u32(const void* p) {
    uint32_t a;
    asm("{ .reg .u64 t; cvta.to.shared.u64 t, %1; cvt.u32.u64 %0, t; }" : "=r"(a) : "l"(p));
    return a;
}
__device__ __forceinline__ void ldm_x4(uint32_t* r, uint32_t addr) {
    asm volatile("ldmatrix.sync.aligned.m8n8.x4.shared.b16 {%0,%1,%2,%3}, [%4];"
        : "=r"(r[0]), "=r"(r[1]), "=r"(r[2]), "=r"(r[3]) : "r"(addr));
}
__device__ __forceinline__ void mma16816(float* d, const uint32_t* a, const uint32_t* b) {
    asm volatile("mma.sync.aligned.m16n8k16.row.col.f32.f16.f16.f32 "
        "{%0,%1,%2,%3}, {%4,%5,%6,%7}, {%8,%9}, {%0,%1,%2,%3};"
        : "+f"(d[0]), "+f"(d[1]), "+f"(d[2]), "+f"(d[3])
        : "r"(a[0]), "r"(a[1]), "r"(a[2]), "r"(a[3]), "r"(b[0]), "r"(b[1]));
}
__device__ __forceinline__ void cp16(uint32_t dst, const void* src) {
    asm volatile("cp.async.cg.shared.global [%0], [%1], 16;" :: "r"(dst), "l"(src));
}
#define CP_COMMIT()  asm volatile("cp.async.commit_group;")
#define CP_WAIT(n)   asm volatile("cp.async.wait_group %0;" :: "n"(n))

// ---------------- L0: zero output + counters ----------------
__global__ void zero_kernel(float* __restrict__ out, int n) {
    int i = blockIdx.x * blockDim.x + threadIdx.x;
    if (i < n) out[i] = 0.0f;
    if (i < NE) g_cnt[i] = 0;
}

// ---------------- L1: routing ----------------
__global__ void route_kernel(const float* __restrict__ logits) {
    int t = blockIdx.x * blockDim.x + threadIdx.x;
    if (t >= T_TOK) return;
    float v[NE];
#pragma unroll
    for (int e = 0; e < NE; ++e) v[e] = logits[t * NE + e];
    int i0 = 0;
#pragma unroll
    for (int e = 1; e < NE; ++e) if (v[e] > v[i0]) i0 = e;
    int i1 = (i0 == 0) ? 1 : 0;
#pragma unroll
    for (int e = 0; e < NE; ++e) if (e != i0 && v[e] > v[i1]) i1 = e;
    float ex = __expf(v[i1] - v[i0]);
    float w0 = 1.0f / (1.0f + ex);
    float w1 = ex * w0;
    int p0 = atomicAdd(&g_cnt[i0], 1);
    g_tok[i0 * T_TOK + p0] = t;  g_rw[i0 * T_TOK + p0] = w0;
    int p1 = atomicAdd(&g_cnt[i1], 1);
    g_tok[i1 * T_TOK + p1] = t;  g_rw[i1 * T_TOK + p1] = w1;
}

// ---------------- L2: x fp32 -> fp16 ----------------
__global__ void convert_x_kernel(const float* __restrict__ x) {
    size_t i = ((size_t)blockIdx.x * 256 + threadIdx.x) * 8;
    float4 a = *(const float4*)(x + i);
    float4 b = *(const float4*)(x + i + 4);
    uint4 o;
    o.x = h2u(__floats2half2_rn(a.x, a.y));
    o.y = h2u(__floats2half2_rn(a.z, a.w));
    o.z = h2u(__floats2half2_rn(b.x, b.y));
    o.w = h2u(__floats2half2_rn(b.z, b.w));
    *(uint4*)(g_x + i) = o;
}

// ---------------- L3/L4: weight dequant (DRAM-roofline bound) ----------------
__global__ void dequant_gu_kernel(const int* __restrict__ q, const float* __restrict__ s) {
    int gid = blockIdx.x * 256 + threadIdx.x;
    int row = gid >> 7;
    int kc  = (gid & 127) << 4;
    const int4* src = (const int4*)(q + (size_t)row * H_DIM + kc);
    float sc = s[row * (H_DIM / GS) + (kc >> 7)];
    uint32_t o[8];
#pragma unroll
    for (int j = 0; j < 4; ++j) {
        int4 v = src[j];
        o[j * 2 + 0] = h2u(__floats2half2_rn(sc * (float)(v.x - 8), sc * (float)(v.y - 8)));
        o[j * 2 + 1] = h2u(__floats2half2_rn(sc * (float)(v.z - 8), sc * (float)(v.w - 8)));
    }
    uint4* dst = (uint4*)(g_wgu + (size_t)row * H_DIM + kc);
    dst[0] = make_uint4(o[0], o[1], o[2], o[3]);
    dst[1] = make_uint4(o[4], o[5], o[6], o[7]);
}

__global__ void dequant_dn_kernel(const int* __restrict__ q, const float* __restrict__ s) {
    int gid = blockIdx.x * 256 + threadIdx.x;
    int row = gid / 88;
    int kc  = (gid - row * 88) << 4;
    const int4* src = (const int4*)(q + (size_t)row * I_DIM + kc);
    float sc = s[row * (I_DIM / GS) + (kc >> 7)];
    uint32_t o[8];
#pragma unroll
    for (int j = 0; j < 4; ++j) {
        int4 v = src[j];
        o[j * 2 + 0] = h2u(__floats2half2_rn(sc * (float)(v.x - 8), sc * (float)(v.y - 8)));
        o[j * 2 + 1] = h2u(__floats2half2_rn(sc * (float)(v.z - 8), sc * (float)(v.w - 8)));
    }
    uint4* dst = (uint4*)(g_wd + (size_t)row * I_DIM + kc);
    dst[0] = make_uint4(o[0], o[1], o[2], o[3]);
    dst[1] = make_uint4(o[4], o[5], o[6], o[7]);
}

// =================================================================
// GEMM1 (unchanged from R9): g_x @ g_wgu^T, fused SwiGLU -> g_act.
// BM=128, BN=64 gate + 64 up, BK=64, 3-stage cp.async.
// =================================================================
__global__ __launch_bounds__(256, 2) void gemm1_kernel() {
    const int e   = blockIdx.z;
    const int cnt = g_cnt[e];
    const int m0  = blockIdx.x * BM;
    if (m0 >= cnt) return;
    const int n0  = blockIdx.y * 64;

    extern __shared__ __half smem[];
    const uint32_t sbase = smem_u32(smem);

    const int tid = threadIdx.x, lane = tid & 31, wid = tid >> 5;
    const int warp_m = wid & 3, warp_n = wid >> 2;

    const int rb = tid >> 3, ch = tid & 7;
    const __half* asrc[4];
    const __half* bsrc[4];
    uint32_t adst[4], bdst[4];
    const int* tokp = g_tok + e * T_TOK;
#pragma unroll
    for (int p = 0; p < 4; ++p) {
        int r = rb + p * 32;
        int m = m0 + r; if (m >= cnt) m = cnt - 1;
        asrc[p] = g_x + (size_t)tokp[m] * H_DIM + ch * 8;
        int grow = (r < 64) ? (n0 + r) : (I_DIM + n0 + r - 64);
        bsrc[p] = g_wgu + ((size_t)e * 2 * I_DIM + grow) * H_DIM + ch * 8;
        adst[p] = (uint32_t)((r * LDSW + ch * 8) * 2);
        bdst[p] = adst[p] + A_OFF_B;
    }

    float accg[2][4][4], accu[2][4][4];
#pragma unroll
    for (int a = 0; a < 2; ++a)
#pragma unroll
        for (int b = 0; b < 4; ++b)
#pragma unroll
            for (int c = 0; c < 4; ++c) { accg[a][b][c] = 0.f; accu[a][b][c] = 0.f; }

    const int arow0 = warp_m * 32 + (lane & 15);
    const int acol  = (lane >> 4) * 8;
    const int brow  = (lane & 7) + ((lane >> 4) << 3);
    const int bcol  = ((lane >> 3) & 1) * 8;

    const int S = H_DIM / BK;   // 32
#pragma unroll
    for (int s = 0; s < 2; ++s) {
        const uint32_t stg = sbase + (uint32_t)(s * STAGE_B);
        const int kb = s * BK;
#pragma unroll
        for (int p = 0; p < 4; ++p) {
            cp16(stg + adst[p], asrc[p] + kb);
            cp16(stg + bdst[p], bsrc[p] + kb);
        }
        CP_COMMIT();
    }

    int buf = 0;
    for (int s = 0; s < S; ++s) {
        CP_WAIT(1);
        __syncthreads();
        if (s + 2 < S) {
            int nb = buf + 2; if (nb >= NSTAGE) nb -= NSTAGE;
            const uint32_t stg = sbase + (uint32_t)(nb * STAGE_B);
            const int kb = (s + 2) * BK;
#pragma unroll
            for (int p = 0; p < 4; ++p) {
                cp16(stg + adst[p], asrc[p] + kb);
                cp16(stg + bdst[p], bsrc[p] + kb);
            }
        }
        CP_COMMIT();

        const uint32_t sa = sbase + (uint32_t)(buf * STAGE_B);
        const uint32_t sb = sa + A_OFF_B;
#pragma unroll
        for (int ks = 0; ks < 4; ++ks) {
            const int kc = ks * 16;
            uint32_t A[2][4], Bg[2][4], Bu[2][4];
            ldm_x4(A[0], sa + (uint32_t)(((arow0     ) * LDSW + kc + acol) * 2));
            ldm_x4(A[1], sa + (uint32_t)(((arow0 + 16) * LDSW + kc + acol) * 2));
#pragma unroll
            for (int bb = 0; bb < 2; ++bb) {
                ldm_x4(Bg[bb], sb + (uint32_t)(((warp_n * 32 + bb * 16 + brow) * LDSW + kc + bcol) * 2));
                ldm_x4(Bu[bb], sb + (uint32_t)(((64 + warp_n * 32 + bb * 16 + brow) * LDSW + kc + bcol) * 2));
            }
#pragma unroll
            for (int mf = 0; mf < 2; ++mf)
#pragma unroll
                for (int nf = 0; nf < 4; ++nf) {
                    mma16816(accg[mf][nf], A[mf], &Bg[nf >> 1][(nf & 1) * 2]);
                    mma16816(accu[mf][nf], A[mf], &Bu[nf >> 1][(nf & 1) * 2]);
                }
        }
        if (++buf == NSTAGE) buf = 0;
    }

#pragma unroll
    for (int mf = 0; mf < 2; ++mf) {
#pragma unroll
        for (int hr = 0; hr < 2; ++hr) {
            const int m = m0 + warp_m * 32 + mf * 16 + (lane >> 2) + hr * 8;
            if (m >= cnt) continue;
            __half* arow = g_act + ((size_t)e * T_TOK + m) * I_DIM;
#pragma unroll
            for (int nf = 0; nf < 4; ++nf) {
                const int c = n0 + warp_n * 32 + nf * 8 + (lane & 3) * 2;
                const float g0 = accg[mf][nf][hr * 2 + 0];
                const float g1 = accg[mf][nf][hr * 2 + 1];
                const float u0 = accu[mf][nf][hr * 2 + 0];
                const float u1 = accu[mf][nf][hr * 2 + 1];
                const float a0 = g0 / (1.0f + __expf(-g0)) * u0;
                const float a1 = g1 / (1.0f + __expf(-g1)) * u1;
                *(__half2*)&arow[c] = __floats2half2_rn(a0, a1);
            }
        }
    }
}

// =================================================================
// GEMM2 (occupancy experiment): g_act @ g_wd^T, BN=64, BK=64,
// 2-stage cp.async, 55.3 KB smem, __launch_bounds__(256,3) -> 24 warps/SM.
// 8 warps: 4(m) x 2(n32). grid (16, 32, 8).
// =================================================================
__global__ __launch_bounds__(256, 3) void gemm2_kernel(float* __restrict__ out) {
    const int e   = blockIdx.z;
    const int cnt = g_cnt[e];
    const int m0  = blockIdx.x * BM;
    if (m0 >= cnt) return;
    const int n0  = blockIdx.y * 64;

    extern __shared__ __half smem[];
    const uint32_t sbase = smem_u32(smem);

    const int tid = threadIdx.x, lane = tid & 31, wid = tid >> 5;
    const int warp_m = wid & 3, warp_n = wid >> 2;

    // A loader: 128 rows x 128B/slab, 2 thr/row, 4 cp16 each
    const int arow = tid >> 1, aseg = tid & 1;
    int am = m0 + arow; if (am >= cnt) am = cnt - 1;
    const __half* asrc = g_act + ((size_t)e * T_TOK + am) * I_DIM + aseg * 32;
    const uint32_t adst = sbase + (uint32_t)(arow * 144 + aseg * 64);
    // B loader: 64 rows x 128B/slab, 4 thr/row, 2 cp16 each
    const int brow = tid >> 2, bseg = tid & 3;
    const __half* bsrc = g_wd + ((size_t)e * H_DIM + n0 + brow) * I_DIM + bseg * 16;
    const uint32_t bdst = sbase + G2_A_ST + (uint32_t)(brow * 144 + bseg * 32);

    float acc[2][4][4];
#pragma unroll
    for (int a = 0; a < 2; ++a)
#pragma unroll
        for (int b = 0; b < 4; ++b)
#pragma unroll
            for (int c = 0; c < 4; ++c) acc[a][b][c] = 0.f;

    const int arow0 = warp_m * 32 + (lane & 15);
    const int acol  = (lane >> 4) * 8;
    const int browl = (lane & 7) + ((lane >> 4) << 3);
    const int bcol  = ((lane >> 3) & 1) * 8;
    const uint32_t aoff0 = (uint32_t)((arow0 * LDSW + acol) * 2);
    const uint32_t aoff1 = (uint32_t)(((arow0 + 16) * LDSW + acol) * 2);
    uint32_t boff[2];
#pragma unroll
    for (int bb = 0; bb < 2; ++bb)
        boff[bb] = (uint32_t)(((warp_n * 32 + bb * 16 + browl) * LDSW + bcol) * 2);

    // prologue: slab 0 -> stage 0
    {
#pragma unroll
        for (int c = 0; c < 4; ++c) cp16(adst + c * 16, asrc + c * 8);
#pragma unroll
        for (int c = 0; c < 2; ++c) cp16(bdst + c * 16, bsrc + c * 8);
        CP_COMMIT();
    }

    const int S = I_DIM / BK;   // 22
    for (int s = 0; s < S; ++s) {
        if (s + 1 < S) {
            const uint32_t stg = (uint32_t)(((s + 1) & 1) * G2_STAGE);
            const int kb = (s + 1) * BK;
#pragma unroll
            for (int c = 0; c < 4; ++c) cp16(adst + stg + c * 16, asrc + kb + c * 8);
#pragma unroll
            for (int c = 0; c < 2; ++c) cp16(bdst + stg + c * 16, bsrc + kb + c * 8);
            CP_COMMIT();
            CP_WAIT(1);
        } else {
            CP_WAIT(0);
        }
        __syncthreads();

        const uint32_t sa = sbase + (uint32_t)((s & 1) * G2_STAGE);
        const uint32_t sb = sa + G2_A_ST;
#pragma unroll
        for (int ks = 0; ks < 4; ++ks) {
            const uint32_t kb2 = (uint32_t)(ks * 32);
            uint32_t A[2][4], B[2][4];
            ldm_x4(A[0], sa + aoff0 + kb2);
            ldm_x4(A[1], sa + aoff1 + kb2);
            ldm_x4(B[0], sb + boff[0] + kb2);
            ldm_x4(B[1], sb + boff[1] + kb2);
#pragma unroll
            for (int mf = 0; mf < 2; ++mf)
#pragma unroll
                for (int nf = 0; nf < 4; ++nf)
                    mma16816(acc[mf][nf], A[mf], &B[nf >> 1][(nf & 1) * 2]);
        }
        __syncthreads();
    }

    // epilogue: route-weighted scatter-add
#pragma unroll
    for (int mf = 0; mf < 2; ++mf) {
#pragma unroll
        for (int hr = 0; hr < 2; ++hr) {
            const int m = m0 + warp_m * 32 + mf * 16 + (lane >> 2) + hr * 8;
            if (m >= cnt) continue;
            const int   tok = g_tok[e * T_TOK + m];
            const float rw  = g_rw [e * T_TOK + m];
            float* orow = out + (size_t)tok * H_DIM;
#pragma unroll
            for (int nf = 0; nf < 4; ++nf) {
                const int c = n0 + warp_n * 32 + nf * 8 + (lane & 3) * 2;
                atomicAdd(&orow[c],     rw * acc[mf][nf][hr * 2 + 0]);
                atomicAdd(&orow[c + 1], rw * acc[mf][nf][hr * 2 + 1]);
            }
        }
    }
}

// ---------------------------------------------------------------
extern "C" void kernel_launch(void* const* d_in, const int* in_sizes, int n_in,
                              void* d_out, int out_size) {
    const float* logits = (const float*)d_in[0];
    const float* x      = (const float*)d_in[1];
    const int*   qgu    = (const int*)  d_in[2];
    const float* sgu    = (const float*)d_in[3];
    const int*   qd     = (const int*)  d_in[4];
    const float* sd     = (const float*)d_in[5];
    float* out = (float*)d_out;

    cudaFuncSetAttribute(gemm1_kernel, cudaFuncAttributeMaxDynamicSharedMemorySize, SMEM_BYTES);
    cudaFuncSetAttribute(gemm2_kernel, cudaFuncAttributeMaxDynamicSharedMemorySize, G2_SMEM);

    const int n_out = T_TOK * H_DIM;
    zero_kernel<<<(n_out + 255) / 256, 256>>>(out, n_out);
    route_kernel<<<(T_TOK + 127) / 128, 128>>>(logits);
    convert_x_kernel<<<2048, 256>>>(x);
    dequant_gu_kernel<<<11264, 256>>>(qgu, sgu);
    dequant_dn_kernel<<<5632, 256>>>(qd, sd);

    dim3 g1(T_TOK / BM, I_DIM / 64, NE);    // (16, 22, 8)
    gemm1_kernel<<<g1, 256, SMEM_BYTES>>>();

    dim3 g2(T_TOK / BM, H_DIM / 64, NE);    // (16, 32, 8)
    gemm2_kernel<<<g2, 256, G2_SMEM>>>(out);
}

// round 12
// speedup vs baseline: 2.2346x; 1.3340x over previous
#include <cuda_runtime.h>
#include <cuda_fp16.h>
#include <stdint.h>
#include <string.h>

#define T_TOK 2048
#define H_DIM 2048
#define I_DIM 1408
#define NE    8
#define GS    128
#define BM    128
#define BK    64
#define LDSW  72                        // smem row stride in halves (144B)
#define A_OFF_B   (128 * LDSW * 2)      // B tile byte offset within a stage
#define STAGE_B   (2 * 128 * LDSW * 2)  // stage bytes (A + B tiles)
#define NSTAGE    3
#define SMEM_BYTES (NSTAGE * STAGE_B)   // 110592 B

// ---- persistent device scratch (no runtime allocation) ----
__device__ int    g_cnt[NE];
__device__ int    g_tok[NE * T_TOK];
__device__ float  g_rw [NE * T_TOK];
__device__ __half g_x  [(size_t)T_TOK * H_DIM];
__device__ __half g_act[(size_t)NE * T_TOK * I_DIM];
__device__ __half g_wgu[(size_t)NE * 2 * I_DIM * H_DIM];  // 92 MB fp16 dequant
__device__ __half g_wd [(size_t)NE * H_DIM * I_DIM];      // 46 MB fp16 dequant

// ---------------- helpers ----------------
__device__ __forceinline__ uint32_t h2u(__half2 h) { uint32_t u; memcpy(&u, &h, 4); return u; }
__device__ __forceinline__ uint32_t smem_u32(const void* p) {
    uint32_t a;
    asm("{ .reg .u64 t; cvta.to.shared.u64 t, %1; cvt.u32.u64 %0, t; }" : "=r"(a) : "l"(p));
    return a;
}
__device__ __forceinline__ void ldm_x4(uint32_t* r, uint32_t addr) {
    asm volatile("ldmatrix.sync.aligned.m8n8.x4.shared.b16 {%0,%1,%2,%3}, [%4];"
        : "=r"(r[0]), "=r"(r[1]), "=r"(r[2]), "=r"(r[3]) : "r"(addr));
}
__device__ __forceinline__ void mma16816(float* d, const uint32_t* a, const uint32_t* b) {
    asm volatile("mma.sync.aligned.m16n8k16.row.col.f32.f16.f16.f32 "
        "{%0,%1,%2,%3}, {%4,%5,%6,%7}, {%8,%9}, {%0,%1,%2,%3};"
        : "+f"(d[0]), "+f"(d[1]), "+f"(d[2]), "+f"(d[3])
        : "r"(a[0]), "r"(a[1]), "r"(a[2]), "r"(a[3]), "r"(b[0]), "r"(b[1]));
}
__device__ __forceinline__ void cp16(uint32_t dst, const void* src) {
    asm volatile("cp.async.cg.shared.global [%0], [%1], 16;" :: "r"(dst), "l"(src));
}
#define CP_COMMIT()  asm volatile("cp.async.commit_group;")
#define CP_WAIT(n)   asm volatile("cp.async.wait_group %0;" :: "n"(n))

// ---------------- L0: zero output + counters ----------------
__global__ void zero_kernel(float* __restrict__ out, int n) {
    int i = blockIdx.x * blockDim.x + threadIdx.x;
    if (i < n) out[i] = 0.0f;
    if (i < NE) g_cnt[i] = 0;
}

// ---------------- L1: routing ----------------
__global__ void route_kernel(const float* __restrict__ logits) {
    int t = blockIdx.x * blockDim.x + threadIdx.x;
    if (t >= T_TOK) return;
    float v[NE];
#pragma unroll
    for (int e = 0; e < NE; ++e) v[e] = logits[t * NE + e];
    int i0 = 0;
#pragma unroll
    for (int e = 1; e < NE; ++e) if (v[e] > v[i0]) i0 = e;
    int i1 = (i0 == 0) ? 1 : 0;
#pragma unroll
    for (int e = 0; e < NE; ++e) if (e != i0 && v[e] > v[i1]) i1 = e;
    float ex = __expf(v[i1] - v[i0]);
    float w0 = 1.0f / (1.0f + ex);
    float w1 = ex * w0;
    int p0 = atomicAdd(&g_cnt[i0], 1);
    g_tok[i0 * T_TOK + p0] = t;  g_rw[i0 * T_TOK + p0] = w0;
    int p1 = atomicAdd(&g_cnt[i1], 1);
    g_tok[i1 * T_TOK + p1] = t;  g_rw[i1 * T_TOK + p1] = w1;
}

// ---------------- L2: dequant gate_up + convert x (fused launch) ----------------
__global__ void prep_gu_kernel(const int* __restrict__ q, const float* __restrict__ s,
                               const float* __restrict__ x) {
    const int bid = blockIdx.x;
    if (bid < 11264) {
        // dequant gate_up
        int gid = bid * 256 + threadIdx.x;
        int row = gid >> 7;
        int kc  = (gid & 127) << 4;
        const int4* src = (const int4*)(q + (size_t)row * H_DIM + kc);
        float sc = s[row * (H_DIM / GS) + (kc >> 7)];
        uint32_t o[8];
#pragma unroll
        for (int j = 0; j < 4; ++j) {
            int4 v = src[j];
            o[j * 2 + 0] = h2u(__floats2half2_rn(sc * (float)(v.x - 8), sc * (float)(v.y - 8)));
            o[j * 2 + 1] = h2u(__floats2half2_rn(sc * (float)(v.z - 8), sc * (float)(v.w - 8)));
        }
        uint4* dst = (uint4*)(g_wgu + (size_t)row * H_DIM + kc);
        dst[0] = make_uint4(o[0], o[1], o[2], o[3]);
        dst[1] = make_uint4(o[4], o[5], o[6], o[7]);
    } else {
        // convert x fp32 -> fp16
        size_t i = ((size_t)(bid - 11264) * 256 + threadIdx.x) * 8;
        float4 a = *(const float4*)(x + i);
        float4 b = *(const float4*)(x + i + 4);
        uint4 o;
        o.x = h2u(__floats2half2_rn(a.x, a.y));
        o.y = h2u(__floats2half2_rn(a.z, a.w));
        o.z = h2u(__floats2half2_rn(b.x, b.y));
        o.w = h2u(__floats2half2_rn(b.z, b.w));
        *(uint4*)(g_x + i) = o;
    }
}

// =================================================================
// GEMM1 + embedded dequant_dn: blockIdx.y==0 slice (16 x 8 = 128 CTAs)
// converts the down weights while the remaining CTAs run the GEMM.
// GEMM: g_x @ g_wgu^T, fused SwiGLU -> g_act.
// BM=128, BN=64 gate + 64 up, BK=64, 3-stage cp.async.
// grid (16, 23, 8): y==0 dequant slice, y-1 in [0,22) gemm ntile.
// =================================================================
__global__ __launch_bounds__(256, 2) void gemm1_kernel(
    const int* __restrict__ qd, const float* __restrict__ sd)
{
    const int e = blockIdx.z;

    if (blockIdx.y == 0) {
        // ---- dequant_dn slice: 128 CTAs cover E*H*I ints, 16/thread ----
        const int cta = blockIdx.z * 16 + blockIdx.x;           // 0..127
        const int nthreads = 128 * 256;
        const int total = NE * H_DIM * (I_DIM / 16);            // chunks of 16
        for (int gid = cta * 256 + threadIdx.x; gid < total; gid += nthreads) {
            int row = gid / 88;
            int kc  = (gid - row * 88) << 4;
            const int4* src = (const int4*)(qd + (size_t)row * I_DIM + kc);
            float sc = sd[row * (I_DIM / GS) + (kc >> 7)];
            uint32_t o[8];
#pragma unroll
            for (int j = 0; j < 4; ++j) {
                int4 v = src[j];
                o[j * 2 + 0] = h2u(__floats2half2_rn(sc * (float)(v.x - 8), sc * (float)(v.y - 8)));
                o[j * 2 + 1] = h2u(__floats2half2_rn(sc * (float)(v.z - 8), sc * (float)(v.w - 8)));
            }
            uint4* dst = (uint4*)(g_wd + (size_t)row * I_DIM + kc);
            dst[0] = make_uint4(o[0], o[1], o[2], o[3]);
            dst[1] = make_uint4(o[4], o[5], o[6], o[7]);
        }
        return;
    }

    const int cnt = g_cnt[e];
    const int m0  = blockIdx.x * BM;
    if (m0 >= cnt) return;
    const int n0  = (blockIdx.y - 1) * 64;

    extern __shared__ __half smem[];
    const uint32_t sbase = smem_u32(smem);

    const int tid = threadIdx.x, lane = tid & 31, wid = tid >> 5;
    const int warp_m = wid & 3, warp_n = wid >> 2;

    const int rb = tid >> 3, ch = tid & 7;
    const __half* asrc[4];
    const __half* bsrc[4];
    uint32_t adst[4], bdst[4];
    const int* tokp = g_tok + e * T_TOK;
#pragma unroll
    for (int p = 0; p < 4; ++p) {
        int r = rb + p * 32;
        int m = m0 + r; if (m >= cnt) m = cnt - 1;
        asrc[p] = g_x + (size_t)tokp[m] * H_DIM + ch * 8;
        int grow = (r < 64) ? (n0 + r) : (I_DIM + n0 + r - 64);
        bsrc[p] = g_wgu + ((size_t)e * 2 * I_DIM + grow) * H_DIM + ch * 8;
        adst[p] = (uint32_t)((r * LDSW + ch * 8) * 2);
        bdst[p] = adst[p] + A_OFF_B;
    }

    float accg[2][4][4], accu[2][4][4];
#pragma unroll
    for (int a = 0; a < 2; ++a)
#pragma unroll
        for (int b = 0; b < 4; ++b)
#pragma unroll
            for (int c = 0; c < 4; ++c) { accg[a][b][c] = 0.f; accu[a][b][c] = 0.f; }

    const int arow0 = warp_m * 32 + (lane & 15);
    const int acol  = (lane >> 4) * 8;
    const int brow  = (lane & 7) + ((lane >> 4) << 3);
    const int bcol  = ((lane >> 3) & 1) * 8;

    const int S = H_DIM / BK;   // 32
#pragma unroll
    for (int s = 0; s < 2; ++s) {
        const uint32_t stg = sbase + (uint32_t)(s * STAGE_B);
        const int kb = s * BK;
#pragma unroll
        for (int p = 0; p < 4; ++p) {
            cp16(stg + adst[p], asrc[p] + kb);
            cp16(stg + bdst[p], bsrc[p] + kb);
        }
        CP_COMMIT();
    }

    int buf = 0;
    for (int s = 0; s < S; ++s) {
        CP_WAIT(1);
        __syncthreads();
        if (s + 2 < S) {
            int nb = buf + 2; if (nb >= NSTAGE) nb -= NSTAGE;
            const uint32_t stg = sbase + (uint32_t)(nb * STAGE_B);
            const int kb = (s + 2) * BK;
#pragma unroll
            for (int p = 0; p < 4; ++p) {
                cp16(stg + adst[p], asrc[p] + kb);
                cp16(stg + bdst[p], bsrc[p] + kb);
            }
        }
        CP_COMMIT();

        const uint32_t sa = sbase + (uint32_t)(buf * STAGE_B);
        const uint32_t sb = sa + A_OFF_B;
#pragma unroll
        for (int ks = 0; ks < 4; ++ks) {
            const int kc = ks * 16;
            uint32_t A[2][4], Bg[2][4], Bu[2][4];
            ldm_x4(A[0], sa + (uint32_t)(((arow0     ) * LDSW + kc + acol) * 2));
            ldm_x4(A[1], sa + (uint32_t)(((arow0 + 16) * LDSW + kc + acol) * 2));
#pragma unroll
            for (int bb = 0; bb < 2; ++bb) {
                ldm_x4(Bg[bb], sb + (uint32_t)(((warp_n * 32 + bb * 16 + brow) * LDSW + kc + bcol) * 2));
                ldm_x4(Bu[bb], sb + (uint32_t)(((64 + warp_n * 32 + bb * 16 + brow) * LDSW + kc + bcol) * 2));
            }
#pragma unroll
            for (int mf = 0; mf < 2; ++mf)
#pragma unroll
                for (int nf = 0; nf < 4; ++nf) {
                    mma16816(accg[mf][nf], A[mf], &Bg[nf >> 1][(nf & 1) * 2]);
                    mma16816(accu[mf][nf], A[mf], &Bu[nf >> 1][(nf & 1) * 2]);
                }
        }
        if (++buf == NSTAGE) buf = 0;
    }

#pragma unroll
    for (int mf = 0; mf < 2; ++mf) {
#pragma unroll
        for (int hr = 0; hr < 2; ++hr) {
            const int m = m0 + warp_m * 32 + mf * 16 + (lane >> 2) + hr * 8;
            if (m >= cnt) continue;
            __half* arow = g_act + ((size_t)e * T_TOK + m) * I_DIM;
#pragma unroll
            for (int nf = 0; nf < 4; ++nf) {
                const int c = n0 + warp_n * 32 + nf * 8 + (lane & 3) * 2;
                const float g0 = accg[mf][nf][hr * 2 + 0];
                const float g1 = accg[mf][nf][hr * 2 + 1];
                const float u0 = accu[mf][nf][hr * 2 + 0];
                const float u1 = accu[mf][nf][hr * 2 + 1];
                const float a0 = g0 / (1.0f + __expf(-g0)) * u0;
                const float a1 = g1 / (1.0f + __expf(-g1)) * u1;
                *(__half2*)&arow[c] = __floats2half2_rn(a0, a1);
            }
        }
    }
}

// =================================================================
// GEMM2 (R9 config): g_act @ g_wd^T, BM=128, BN=128, BK=64,
// 3-stage cp.async, route-weighted atomicAdd into out.
// =================================================================
__global__ __launch_bounds__(256, 2) void gemm2_kernel(float* __restrict__ out) {
    const int e   = blockIdx.z;
    const int cnt = g_cnt[e];
    const int m0  = blockIdx.x * BM;
    if (m0 >= cnt) return;
    const int n0  = blockIdx.y * 128;

    extern __shared__ __half smem[];
    const uint32_t sbase = smem_u32(smem);

    const int tid = threadIdx.x, lane = tid & 31, wid = tid >> 5;
    const int warp_m = wid & 3, warp_n = wid >> 2;

    const int rb = tid >> 3, ch = tid & 7;
    const __half* asrc[4];
    const __half* bsrc[4];
    uint32_t adst[4], bdst[4];
#pragma unroll
    for (int p = 0; p < 4; ++p) {
        int r = rb + p * 32;
        int m = m0 + r; if (m >= cnt) m = cnt - 1;
        asrc[p] = g_act + ((size_t)e * T_TOK + m) * I_DIM + ch * 8;
        bsrc[p] = g_wd + ((size_t)e * H_DIM + n0 + r) * I_DIM + ch * 8;
        adst[p] = (uint32_t)((r * LDSW + ch * 8) * 2);
        bdst[p] = adst[p] + A_OFF_B;
    }

    float acc[2][8][4];
#pragma unroll
    for (int a = 0; a < 2; ++a)
#pragma unroll
        for (int b = 0; b < 8; ++b)
#pragma unroll
            for (int c = 0; c < 4; ++c) acc[a][b][c] = 0.f;

    const int arow0 = warp_m * 32 + (lane & 15);
    const int acol  = (lane >> 4) * 8;
    const int brow  = (lane & 7) + ((lane >> 4) << 3);
    const int bcol  = ((lane >> 3) & 1) * 8;

    const int S = I_DIM / BK;   // 22
#pragma unroll
    for (int s = 0; s < 2; ++s) {
        const uint32_t stg = sbase + (uint32_t)(s * STAGE_B);
        const int kb = s * BK;
#pragma unroll
        for (int p = 0; p < 4; ++p) {
            cp16(stg + adst[p], asrc[p] + kb);
            cp16(stg + bdst[p], bsrc[p] + kb);
        }
        CP_COMMIT();
    }

    int buf = 0;
    for (int s = 0; s < S; ++s) {
        CP_WAIT(1);
        __syncthreads();
        if (s + 2 < S) {
            int nb = buf + 2; if (nb >= NSTAGE) nb -= NSTAGE;
            const uint32_t stg = sbase + (uint32_t)(nb * STAGE_B);
            const int kb = (s + 2) * BK;
#pragma unroll
            for (int p = 0; p < 4; ++p) {
                cp16(stg + adst[p], asrc[p] + kb);
                cp16(stg + bdst[p], bsrc[p] + kb);
            }
        }
        CP_COMMIT();

        const uint32_t sa = sbase + (uint32_t)(buf * STAGE_B);
        const uint32_t sb = sa + A_OFF_B;
#pragma unroll
        for (int ks = 0; ks < 4; ++ks) {
            const int kc = ks * 16;
            uint32_t A[2][4], B[4][4];
            ldm_x4(A[0], sa + (uint32_t)(((arow0     ) * LDSW + kc + acol) * 2));
            ldm_x4(A[1], sa + (uint32_t)(((arow0 + 16) * LDSW + kc + acol) * 2));
#pragma unroll
            for (int bb = 0; bb < 4; ++bb)
                ldm_x4(B[bb], sb + (uint32_t)(((warp_n * 64 + bb * 16 + brow) * LDSW + kc + bcol) * 2));
#pragma unroll
            for (int mf = 0; mf < 2; ++mf)
#pragma unroll
                for (int nf = 0; nf < 8; ++nf)
                    mma16816(acc[mf][nf], A[mf], &B[nf >> 1][(nf & 1) * 2]);
        }
        if (++buf == NSTAGE) buf = 0;
    }

#pragma unroll
    for (int mf = 0; mf < 2; ++mf) {
#pragma unroll
        for (int hr = 0; hr < 2; ++hr) {
            const int m = m0 + warp_m * 32 + mf * 16 + (lane >> 2) + hr * 8;
            if (m >= cnt) continue;
            const int   tok = g_tok[e * T_TOK + m];
            const float rw  = g_rw [e * T_TOK + m];
            float* orow = out + (size_t)tok * H_DIM;
#pragma unroll
            for (int nf = 0; nf < 8; ++nf) {
                const int c = n0 + warp_n * 64 + nf * 8 + (lane & 3) * 2;
                atomicAdd(&orow[c],     rw * acc[mf][nf][hr * 2 + 0]);
                atomicAdd(&orow[c + 1], rw * acc[mf][nf][hr * 2 + 1]);
            }
        }
    }
}

// ---------------------------------------------------------------
extern "C" void kernel_launch(void* const* d_in, const int* in_sizes, int n_in,
                              void* d_out, int out_size) {
    const float* logits = (const float*)d_in[0];
    const float* x      = (const float*)d_in[1];
    const int*   qgu    = (const int*)  d_in[2];
    const float* sgu    = (const float*)d_in[3];
    const int*   qd     = (const int*)  d_in[4];
    const float* sd     = (const float*)d_in[5];
    float* out = (float*)d_out;

    cudaFuncSetAttribute(gemm1_kernel, cudaFuncAttributeMaxDynamicSharedMemorySize, SMEM_BYTES);
    cudaFuncSetAttribute(gemm2_kernel, cudaFuncAttributeMaxDynamicSharedMemorySize, SMEM_BYTES);

    const int n_out = T_TOK * H_DIM;
    zero_kernel<<<(n_out + 255) / 256, 256>>>(out, n_out);
    route_kernel<<<(T_TOK + 127) / 128, 128>>>(logits);
    prep_gu_kernel<<<11264 + 2048, 256>>>(qgu, sgu, x);   // dequant gate_up + convert x

    dim3 g1(T_TOK / BM, I_DIM / 64 + 1, NE);   // (16, 23, 8): y==0 = dequant_dn slice
    gemm1_kernel<<<g1, 256, SMEM_BYTES>>>(qd, sd);

    dim3 g2(T_TOK / BM, H_DIM / 128, NE);      // (16, 16, 8)
    gemm2_kernel<<<g2, 256, SMEM_BYTES>>>(out);
}

// round 14
// speedup vs baseline: 2.2914x; 1.0254x over previous
#include <cuda_runtime.h>
#include <cuda_fp16.h>
#include <stdint.h>
#include <string.h>

#define T_TOK 2048
#define H_DIM 2048
#define I_DIM 1408
#define NE    8
#define GS    128
#define BM    128
#define BK    64
#define LDSW  72                        // smem row stride in halves (144B)
#define A_OFF_B   (128 * LDSW * 2)      // B tile byte offset within a stage
#define STAGE_B   (2 * 128 * LDSW * 2)  // stage bytes (A + B tiles)
#define NSTAGE    3
#define SMEM_BYTES (NSTAGE * STAGE_B)   // 110592 B

// prep grid partition
#define NB_GU   11264                   // gate_up dequant blocks
#define NB_X    2048                    // convert_x blocks
#define NB_Z    4096                    // zero-out blocks (float4 each thread)

// ---- persistent device scratch (no runtime allocation) ----
__device__ int    g_cnt[NE];
__device__ int    g_tok[NE * T_TOK];
__device__ float  g_rw [NE * T_TOK];
__device__ __half g_x  [(size_t)T_TOK * H_DIM];
__device__ __half g_act[(size_t)NE * T_TOK * I_DIM];
__device__ __half g_wgu[(size_t)NE * 2 * I_DIM * H_DIM];  // 92 MB fp16 dequant
__device__ __half g_wd [(size_t)NE * H_DIM * I_DIM];      // 46 MB fp16 dequant

// ---------------- helpers ----------------
__device__ __forceinline__ uint32_t h2u(__half2 h) { uint32_t u; memcpy(&u, &h, 4); return u; }
__device__ __forceinline__ uint32_t smem_u32(const void* p) {
    uint32_t a;
    asm("{ .reg .u64 t; cvta.to.shared.u64 t, %1; cvt.u32.u64 %0, t; }" : "=r"(a) : "l"(p));
    return a;
}
__device__ __forceinline__ void ldm_x4(uint32_t* r, uint32_t addr) {
    asm volatile("ldmatrix.sync.aligned.m8n8.x4.shared.b16 {%0,%1,%2,%3}, [%4];"
        : "=r"(r[0]), "=r"(r[1]), "=r"(r[2]), "=r"(r[3]) : "r"(addr));
}
__device__ __forceinline__ void mma16816(float* d, const uint32_t* a, const uint32_t* b) {
    asm volatile("mma.sync.aligned.m16n8k16.row.col.f32.f16.f16.f32 "
        "{%0,%1,%2,%3}, {%4,%5,%6,%7}, {%8,%9}, {%0,%1,%2,%3};"
        : "+f"(d[0]), "+f"(d[1]), "+f"(d[2]), "+f"(d[3])
        : "r"(a[0]), "r"(a[1]), "r"(a[2]), "r"(a[3]), "r"(b[0]), "r"(b[1]));
}
__device__ __forceinline__ void cp16(uint32_t dst, const void* src) {
    asm volatile("cp.async.cg.shared.global [%0], [%1], 16;" :: "r"(dst), "l"(src));
}
#define CP_COMMIT()  asm volatile("cp.async.commit_group;")
#define CP_WAIT(n)   asm volatile("cp.async.wait_group %0;" :: "n"(n))

// ---------------- L0: routing (single block -> no zero dependency) ----------------
__global__ __launch_bounds__(1024) void route_kernel(const float* __restrict__ logits) {
    __shared__ int scnt[NE];
    const int tid = threadIdx.x;
    if (tid < NE) scnt[tid] = 0;
    __syncthreads();
    for (int t = tid; t < T_TOK; t += 1024) {
        float v[NE];
#pragma unroll
        for (int e = 0; e < NE; ++e) v[e] = logits[t * NE + e];
        int i0 = 0;
#pragma unroll
        for (int e = 1; e < NE; ++e) if (v[e] > v[i0]) i0 = e;
        int i1 = (i0 == 0) ? 1 : 0;
#pragma unroll
        for (int e = 0; e < NE; ++e) if (e != i0 && v[e] > v[i1]) i1 = e;
        float ex = __expf(v[i1] - v[i0]);
        float w0 = 1.0f / (1.0f + ex);
        float w1 = ex * w0;
        int p0 = atomicAdd(&scnt[i0], 1);
        g_tok[i0 * T_TOK + p0] = t;  g_rw[i0 * T_TOK + p0] = w0;
        int p1 = atomicAdd(&scnt[i1], 1);
        g_tok[i1 * T_TOK + p1] = t;  g_rw[i1 * T_TOK + p1] = w1;
    }
    __syncthreads();
    if (tid < NE) g_cnt[tid] = scnt[tid];
}

// ---------------- L1: prep = gate_up dequant | convert_x | zero out ----------------
__global__ void prep_kernel(const int* __restrict__ q, const float* __restrict__ s,
                            const float* __restrict__ x, float* __restrict__ out) {
    const int bid = blockIdx.x;
    if (bid < NB_GU) {
        int gid = bid * 256 + threadIdx.x;
        int row = gid >> 7;
        int kc  = (gid & 127) << 4;
        const int4* src = (const int4*)(q + (size_t)row * H_DIM + kc);
        float sc = s[row * (H_DIM / GS) + (kc >> 7)];
        uint32_t o[8];
#pragma unroll
        for (int j = 0; j < 4; ++j) {
            int4 v = src[j];
            o[j * 2 + 0] = h2u(__floats2half2_rn(sc * (float)(v.x - 8), sc * (float)(v.y - 8)));
            o[j * 2 + 1] = h2u(__floats2half2_rn(sc * (float)(v.z - 8), sc * (float)(v.w - 8)));
        }
        uint4* dst = (uint4*)(g_wgu + (size_t)row * H_DIM + kc);
        dst[0] = make_uint4(o[0], o[1], o[2], o[3]);
        dst[1] = make_uint4(o[4], o[5], o[6], o[7]);
    } else if (bid < NB_GU + NB_X) {
        size_t i = ((size_t)(bid - NB_GU) * 256 + threadIdx.x) * 8;
        float4 a = *(const float4*)(x + i);
        float4 b = *(const float4*)(x + i + 4);
        uint4 o;
        o.x = h2u(__floats2half2_rn(a.x, a.y));
        o.y = h2u(__floats2half2_rn(a.z, a.w));
        o.z = h2u(__floats2half2_rn(b.x, b.y));
        o.w = h2u(__floats2half2_rn(b.z, b.w));
        *(uint4*)(g_x + i) = o;
    } else {
        size_t i = ((size_t)(bid - NB_GU - NB_X) * 256 + threadIdx.x) * 4;
        *(float4*)(out + i) = make_float4(0.f, 0.f, 0.f, 0.f);
    }
}

// =================================================================
// GEMM1 (R12) + embedded dequant_dn slice (blockIdx.y==0).
// GEMM: g_x @ g_wgu^T, fused SwiGLU -> g_act.
// BM=128, BN=64 gate + 64 up, BK=64, 3-stage cp.async.
// grid (16, 23, 8): y==0 dequant slice, y-1 in [0,22) gemm ntile.
// =================================================================
__global__ __launch_bounds__(256, 2) void gemm1_kernel(
    const int* __restrict__ qd, const float* __restrict__ sd)
{
    const int e = blockIdx.z;

    if (blockIdx.y == 0) {
        const int cta = blockIdx.z * 16 + blockIdx.x;           // 0..127
        const int nthreads = 128 * 256;
        const int total = NE * H_DIM * (I_DIM / 16);
        for (int gid = cta * 256 + threadIdx.x; gid < total; gid += nthreads) {
            int row = gid / 88;
            int kc  = (gid - row * 88) << 4;
            const int4* src = (const int4*)(qd + (size_t)row * I_DIM + kc);
            float sc = sd[row * (I_DIM / GS) + (kc >> 7)];
            uint32_t o[8];
#pragma unroll
            for (int j = 0; j < 4; ++j) {
                int4 v = src[j];
                o[j * 2 + 0] = h2u(__floats2half2_rn(sc * (float)(v.x - 8), sc * (float)(v.y - 8)));
                o[j * 2 + 1] = h2u(__floats2half2_rn(sc * (float)(v.z - 8), sc * (float)(v.w - 8)));
            }
            uint4* dst = (uint4*)(g_wd + (size_t)row * I_DIM + kc);
            dst[0] = make_uint4(o[0], o[1], o[2], o[3]);
            dst[1] = make_uint4(o[4], o[5], o[6], o[7]);
        }
        return;
    }

    const int cnt = g_cnt[e];
    const int m0  = blockIdx.x * BM;
    if (m0 >= cnt) return;
    const int n0  = (blockIdx.y - 1) * 64;

    extern __shared__ __half smem[];
    const uint32_t sbase = smem_u32(smem);

    const int tid = threadIdx.x, lane = tid & 31, wid = tid >> 5;
    const int warp_m = wid & 3, warp_n = wid >> 2;

    const int rb = tid >> 3, ch = tid & 7;
    const __half* asrc[4];
    const __half* bsrc[4];
    uint32_t adst[4], bdst[4];
    const int* tokp = g_tok + e * T_TOK;
#pragma unroll
    for (int p = 0; p < 4; ++p) {
        int r = rb + p * 32;
        int m = m0 + r; if (m >= cnt) m = cnt - 1;
        asrc[p] = g_x + (size_t)tokp[m] * H_DIM + ch * 8;
        int grow = (r < 64) ? (n0 + r) : (I_DIM + n0 + r - 64);
        bsrc[p] = g_wgu + ((size_t)e * 2 * I_DIM + grow) * H_DIM + ch * 8;
        adst[p] = (uint32_t)((r * LDSW + ch * 8) * 2);
        bdst[p] = adst[p] + A_OFF_B;
    }

    float accg[2][4][4], accu[2][4][4];
#pragma unroll
    for (int a = 0; a < 2; ++a)
#pragma unroll
        for (int b = 0; b < 4; ++b)
#pragma unroll
            for (int c = 0; c < 4; ++c) { accg[a][b][c] = 0.f; accu[a][b][c] = 0.f; }

    const int arow0 = warp_m * 32 + (lane & 15);
    const int acol  = (lane >> 4) * 8;
    const int brow  = (lane & 7) + ((lane >> 4) << 3);
    const int bcol  = ((lane >> 3) & 1) * 8;

    const int S = H_DIM / BK;   // 32
#pragma unroll
    for (int s = 0; s < 2; ++s) {
        const uint32_t stg = sbase + (uint32_t)(s * STAGE_B);
        const int kb = s * BK;
#pragma unroll
        for (int p = 0; p < 4; ++p) {
            cp16(stg + adst[p], asrc[p] + kb);
            cp16(stg + bdst[p], bsrc[p] + kb);
        }
        CP_COMMIT();
    }

    int buf = 0;
    for (int s = 0; s < S; ++s) {
        CP_WAIT(1);
        __syncthreads();
        if (s + 2 < S) {
            int nb = buf + 2; if (nb >= NSTAGE) nb -= NSTAGE;
            const uint32_t stg = sbase + (uint32_t)(nb * STAGE_B);
            const int kb = (s + 2) * BK;
#pragma unroll
            for (int p = 0; p < 4; ++p) {
                cp16(stg + adst[p], asrc[p] + kb);
                cp16(stg + bdst[p], bsrc[p] + kb);
            }
        }
        CP_COMMIT();

        const uint32_t sa = sbase + (uint32_t)(buf * STAGE_B);
        const uint32_t sb = sa + A_OFF_B;
#pragma unroll
        for (int ks = 0; ks < 4; ++ks) {
            const int kc = ks * 16;
            uint32_t A[2][4], Bg[2][4], Bu[2][4];
            ldm_x4(A[0], sa + (uint32_t)(((arow0     ) * LDSW + kc + acol) * 2));
            ldm_x4(A[1], sa + (uint32_t)(((arow0 + 16) * LDSW + kc + acol) * 2));
#pragma unroll
            for (int bb = 0; bb < 2; ++bb) {
                ldm_x4(Bg[bb], sb + (uint32_t)(((warp_n * 32 + bb * 16 + brow) * LDSW + kc + bcol) * 2));
                ldm_x4(Bu[bb], sb + (uint32_t)(((64 + warp_n * 32 + bb * 16 + brow) * LDSW + kc + bcol) * 2));
            }
#pragma unroll
            for (int mf = 0; mf < 2; ++mf)
#pragma unroll
                for (int nf = 0; nf < 4; ++nf) {
                    mma16816(accg[mf][nf], A[mf], &Bg[nf >> 1][(nf & 1) * 2]);
                    mma16816(accu[mf][nf], A[mf], &Bu[nf >> 1][(nf & 1) * 2]);
                }
        }
        if (++buf == NSTAGE) buf = 0;
    }

#pragma unroll
    for (int mf = 0; mf < 2; ++mf) {
#pragma unroll
        for (int hr = 0; hr < 2; ++hr) {
            const int m = m0 + warp_m * 32 + mf * 16 + (lane >> 2) + hr * 8;
            if (m >= cnt) continue;
            __half* arow = g_act + ((size_t)e * T_TOK + m) * I_DIM;
#pragma unroll
            for (int nf = 0; nf < 4; ++nf) {
                const int c = n0 + warp_n * 32 + nf * 8 + (lane & 3) * 2;
                const float g0 = accg[mf][nf][hr * 2 + 0];
                const float g1 = accg[mf][nf][hr * 2 + 1];
                const float u0 = accu[mf][nf][hr * 2 + 0];
                const float u1 = accu[mf][nf][hr * 2 + 1];
                const float a0 = g0 / (1.0f + __expf(-g0)) * u0;
                const float a1 = g1 / (1.0f + __expf(-g1)) * u1;
                *(__half2*)&arow[c] = __floats2half2_rn(a0, a1);
            }
        }
    }
}

// =================================================================
// GEMM2 (R12): g_act @ g_wd^T, BM=128, BN=128, BK=64,
// 3-stage cp.async, route-weighted atomicAdd into out.
// =================================================================
__global__ __launch_bounds__(256, 2) void gemm2_kernel(float* __restrict__ out) {
    const int e   = blockIdx.z;
    const int cnt = g_cnt[e];
    const int m0  = blockIdx.x * BM;
    if (m0 >= cnt) return;
    const int n0  = blockIdx.y * 128;

    extern __shared__ __half smem[];
    const uint32_t sbase = smem_u32(smem);

    const int tid = threadIdx.x, lane = tid & 31, wid = tid >> 5;
    const int warp_m = wid & 3, warp_n = wid >> 2;

    const int rb = tid >> 3, ch = tid & 7;
    const __half* asrc[4];
    const __half* bsrc[4];
    uint32_t adst[4], bdst[4];
#pragma unroll
    for (int p = 0; p < 4; ++p) {
        int r = rb + p * 32;
        int m = m0 + r; if (m >= cnt) m = cnt - 1;
        asrc[p] = g_act + ((size_t)e * T_TOK + m) * I_DIM + ch * 8;
        bsrc[p] = g_wd + ((size_t)e * H_DIM + n0 + r) * I_DIM + ch * 8;
        adst[p] = (uint32_t)((r * LDSW + ch * 8) * 2);
        bdst[p] = adst[p] + A_OFF_B;
    }

    float acc[2][8][4];
#pragma unroll
    for (int a = 0; a < 2; ++a)
#pragma unroll
        for (int b = 0; b < 8; ++b)
#pragma unroll
            for (int c = 0; c < 4; ++c) acc[a][b][c] = 0.f;

    const int arow0 = warp_m * 32 + (lane & 15);
    const int acol  = (lane >> 4) * 8;
    const int brow  = (lane & 7) + ((lane >> 4) << 3);
    const int bcol  = ((lane >> 3) & 1) * 8;

    const int S = I_DIM / BK;   // 22
#pragma unroll
    for (int s = 0; s < 2; ++s) {
        const uint32_t stg = sbase + (uint32_t)(s * STAGE_B);
        const int kb = s * BK;
#pragma unroll
        for (int p = 0; p < 4; ++p) {
            cp16(stg + adst[p], asrc[p] + kb);
            cp16(stg + bdst[p], bsrc[p] + kb);
        }
        CP_COMMIT();
    }

    int buf = 0;
    for (int s = 0; s < S; ++s) {
        CP_WAIT(1);
        __syncthreads();
        if (s + 2 < S) {
            int nb = buf + 2; if (nb >= NSTAGE) nb -= NSTAGE;
            const uint32_t stg = sbase + (uint32_t)(nb * STAGE_B);
            const int kb = (s + 2) * BK;
#pragma unroll
            for (int p = 0; p < 4; ++p) {
                cp16(stg + adst[p], asrc[p] + kb);
                cp16(stg + bdst[p], bsrc[p] + kb);
            }
        }
        CP_COMMIT();

        const uint32_t sa = sbase + (uint32_t)(buf * STAGE_B);
        const uint32_t sb = sa + A_OFF_B;
#pragma unroll
        for (int ks = 0; ks < 4; ++ks) {
            const int kc = ks * 16;
            uint32_t A[2][4], B[4][4];
            ldm_x4(A[0], sa + (uint32_t)(((arow0     ) * LDSW + kc + acol) * 2));
            ldm_x4(A[1], sa + (uint32_t)(((arow0 + 16) * LDSW + kc + acol) * 2));
#pragma unroll
            for (int bb = 0; bb < 4; ++bb)
                ldm_x4(B[bb], sb + (uint32_t)(((warp_n * 64 + bb * 16 + brow) * LDSW + kc + bcol) * 2));
#pragma unroll
            for (int mf = 0; mf < 2; ++mf)
#pragma unroll
                for (int nf = 0; nf < 8; ++nf)
                    mma16816(acc[mf][nf], A[mf], &B[nf >> 1][(nf & 1) * 2]);
        }
        if (++buf == NSTAGE) buf = 0;
    }

#pragma unroll
    for (int mf = 0; mf < 2; ++mf) {
#pragma unroll
        for (int hr = 0; hr < 2; ++hr) {
            const int m = m0 + warp_m * 32 + mf * 16 + (lane >> 2) + hr * 8;
            if (m >= cnt) continue;
            const int   tok = g_tok[e * T_TOK + m];
            const float rw  = g_rw [e * T_TOK + m];
            float* orow = out + (size_t)tok * H_DIM;
#pragma unroll
            for (int nf = 0; nf < 8; ++nf) {
                const int c = n0 + warp_n * 64 + nf * 8 + (lane & 3) * 2;
                atomicAdd(&orow[c],     rw * acc[mf][nf][hr * 2 + 0]);
                atomicAdd(&orow[c + 1], rw * acc[mf][nf][hr * 2 + 1]);
            }
        }
    }
}

// ---------------------------------------------------------------
extern "C" void kernel_launch(void* const* d_in, const int* in_sizes, int n_in,
                              void* d_out, int out_size) {
    const float* logits = (const float*)d_in[0];
    const float* x      = (const float*)d_in[1];
    const int*   qgu    = (const int*)  d_in[2];
    const float* sgu    = (const float*)d_in[3];
    const int*   qd     = (const int*)  d_in[4];
    const float* sd     = (const float*)d_in[5];
    float* out = (float*)d_out;

    cudaFuncSetAttribute(gemm1_kernel, cudaFuncAttributeMaxDynamicSharedMemorySize, SMEM_BYTES);
    cudaFuncSetAttribute(gemm2_kernel, cudaFuncAttributeMaxDynamicSharedMemorySize, SMEM_BYTES);

    route_kernel<<<1, 1024>>>(logits);
    prep_kernel<<<NB_GU + NB_X + NB_Z, 256>>>(qgu, sgu, x, out);

    dim3 g1(T_TOK / BM, I_DIM / 64 + 1, NE);   // (16, 23, 8): y==0 = dequant_dn slice
    gemm1_kernel<<<g1, 256, SMEM_BYTES>>>(qd, sd);

    dim3 g2(T_TOK / BM, H_DIM / 128, NE);      // (16, 16, 8)
    gemm2_kernel<<<g2, 256, SMEM_BYTES>>>(out);
}